// round 4
// baseline (speedup 1.0000x reference)
#include <cuda_runtime.h>

// Shape fixed by the reference: B=1, T=2,000,000, C=16 -> 32M floats.
#define NCOL 16
#define NB   1184   // 8 waves of 148 SMs
#define NT   256

// Graph-replay-safe scratch: __device__ globals (no allocation allowed).
__device__ float        g_sum[NCOL];
__device__ unsigned int g_cnt[NCOL];

// ---------------------------------------------------------------------------
// 1) Zero the accumulators (must run on every graph replay).
// ---------------------------------------------------------------------------
__global__ void k_init() {
    int i = threadIdx.x;
    if (i < NCOL) {
        g_sum[i] = 0.0f;
        g_cnt[i] = 0u;
    }
}

// Branch-free accumulate of one float4 into 4 col-group accumulators.
__device__ __forceinline__ void acc4(float4 v,
                                     float& s0, float& s1, float& s2, float& s3,
                                     unsigned& c0, unsigned& c1, unsigned& c2, unsigned& c3) {
    bool v0 = (v.x == v.x), v1 = (v.y == v.y), v2 = (v.z == v.z), v3 = (v.w == v.w);
    s0 += v0 ? v.x : 0.0f;  c0 += v0;
    s1 += v1 ? v.y : 0.0f;  c1 += v1;
    s2 += v2 ? v.z : 0.0f;  c2 += v2;
    s3 += v3 ? v.w : 0.0f;  c3 += v3;
}

// ---------------------------------------------------------------------------
// 2) Reduce: per-column sum of valid entries + valid count.
//    Grid-stride over float4; stride is a multiple of 4 so each thread's
//    float4 always covers the same 4-column group: cols [(p&3)*4 .. +3].
//    Unrolled x4 with front-batched loads -> MLP_p1 = 4 per thread.
// ---------------------------------------------------------------------------
__global__ void __launch_bounds__(NT) k_reduce(const float4* __restrict__ in4, int n4) {
    __shared__ float        ssum[NCOL];
    __shared__ unsigned int scnt[NCOL];
    if (threadIdx.x < NCOL) {
        ssum[threadIdx.x] = 0.0f;
        scnt[threadIdx.x] = 0u;
    }
    __syncthreads();

    const int tid    = blockIdx.x * NT + threadIdx.x;
    const int stride = NB * NT;           // multiple of 4

    float    s0 = 0.f, s1 = 0.f, s2 = 0.f, s3 = 0.f;
    unsigned c0 = 0u,  c1 = 0u,  c2 = 0u,  c3 = 0u;

    int p = tid;
    // Main unrolled loop: 4 independent 16B loads issued back-to-back.
    for (; p + 3 * stride < n4; p += 4 * stride) {
        float4 a = in4[p];
        float4 b = in4[p + stride];
        float4 c = in4[p + 2 * stride];
        float4 d = in4[p + 3 * stride];
        acc4(a, s0, s1, s2, s3, c0, c1, c2, c3);
        acc4(b, s0, s1, s2, s3, c0, c1, c2, c3);
        acc4(c, s0, s1, s2, s3, c0, c1, c2, c3);
        acc4(d, s0, s1, s2, s3, c0, c1, c2, c3);
    }
    // Tail.
    for (; p < n4; p += stride) {
        acc4(in4[p], s0, s1, s2, s3, c0, c1, c2, c3);
    }

    // Warp tree-reduce across lanes of the same residue class (lane % 4).
    #pragma unroll
    for (int off = 16; off >= 4; off >>= 1) {
        s0 += __shfl_down_sync(0xffffffffu, s0, off);
        s1 += __shfl_down_sync(0xffffffffu, s1, off);
        s2 += __shfl_down_sync(0xffffffffu, s2, off);
        s3 += __shfl_down_sync(0xffffffffu, s3, off);
        c0 += __shfl_down_sync(0xffffffffu, c0, off);
        c1 += __shfl_down_sync(0xffffffffu, c1, off);
        c2 += __shfl_down_sync(0xffffffffu, c2, off);
        c3 += __shfl_down_sync(0xffffffffu, c3, off);
    }

    const int lane = threadIdx.x & 31;
    if (lane < 4) {
        const int base = lane * 4;        // column group of this residue class
        atomicAdd(&ssum[base + 0], s0);
        atomicAdd(&ssum[base + 1], s1);
        atomicAdd(&ssum[base + 2], s2);
        atomicAdd(&ssum[base + 3], s3);
        atomicAdd(&scnt[base + 0], c0);
        atomicAdd(&scnt[base + 1], c1);
        atomicAdd(&scnt[base + 2], c2);
        atomicAdd(&scnt[base + 3], c3);
    }
    __syncthreads();

    if (threadIdx.x < NCOL) {
        atomicAdd(&g_sum[threadIdx.x], ssum[threadIdx.x]);
        atomicAdd(&g_cnt[threadIdx.x], scnt[threadIdx.x]);
    }
}

// ---------------------------------------------------------------------------
// 3) Fill: out = isnan(x) ? mean[col] : x.
//    Mean computed inline from g_sum/g_cnt (cost hidden behind first DRAM
//    load; saves a separate kernel launch). Iterate in REVERSE so the first
//    bytes read are the L2-hot tail left by k_reduce's sequential scan.
//    Output stores use streaming hint (__stcs) so write-allocate doesn't
//    evict the input from L2.
// ---------------------------------------------------------------------------
__global__ void __launch_bounds__(NT) k_fill(const float4* __restrict__ in4,
                                             float4* __restrict__ out4, int n4) {
    const int tid    = blockIdx.x * NT + threadIdx.x;
    const int stride = NB * NT;           // multiple of 4

    int p = (n4 - 1) - tid;
    if (p < 0) return;

    // Fixed column group per thread (p mod 4 is invariant under -= stride).
    const int base = (p & 3) * 4;
    float4 m;
    m.x = g_sum[base + 0] / fmaxf((float)g_cnt[base + 0], 1.0f);
    m.y = g_sum[base + 1] / fmaxf((float)g_cnt[base + 1], 1.0f);
    m.z = g_sum[base + 2] / fmaxf((float)g_cnt[base + 2], 1.0f);
    m.w = g_sum[base + 3] / fmaxf((float)g_cnt[base + 3], 1.0f);

    for (; p >= 0; p -= stride) {
        float4 v = in4[p];
        if (!(v.x == v.x)) v.x = m.x;
        if (!(v.y == v.y)) v.y = m.y;
        if (!(v.z == v.z)) v.z = m.z;
        if (!(v.w == v.w)) v.w = m.w;
        __stcs(&out4[p], v);
    }
}

// ---------------------------------------------------------------------------
extern "C" void kernel_launch(void* const* d_in, const int* in_sizes, int n_in,
                              void* d_out, int out_size) {
    const float4* in4  = (const float4*)d_in[0];
    float4*       out4 = (float4*)d_out;
    const int n4 = in_sizes[0] / 4;   // 32M floats -> 8M float4 (C=16 divides evenly)

    k_init<<<1, 32>>>();
    k_reduce<<<NB, NT>>>(in4, n4);
    k_fill<<<NB, NT>>>(in4, out4, n4);
}